// round 8
// baseline (speedup 1.0000x reference)
#include <cuda_runtime.h>
#include <cstdint>

#define NUM_CLASSES 32
#define MAX_DET     100
#define CONF        0.25f
#define IOU_C       0.45f
#define HC          1.4901161193847656e-8f   // 2^-26 = half-ulp(0.45f)
#define BATCH       64
#define ANCHORS     8400
#define NT          384
#define KPT         12
#define HALF        (NT * KPT)               // 4608 anchors per CTA
#define PADDED      (2 * HALF)               // 9216
#define NWARPS      (NT / 32)                // 12
#define NEG_INF_I   ((int)0x80000000)
#define IDX_SENT    0x7FFFFFFF

#define P1_NT       512
#define P1_GRIDX    (PADDED / P1_NT)         // 18

// scratch (allocation-free rule: __device__ globals)
__device__ float4 g_box[BATCH * PADDED];
__device__ float  g_sc [BATCH * PADDED];
__device__ float  g_cls[BATCH * PADDED];

// NMS dynamic smem per CTA: FULL float4 boxes[9216] | FULL float cls[9216]
#define SMEM_BYTES (PADDED * 16 + PADDED * 4)

// ---------------- helpers ----------------
__device__ __forceinline__ uint32_t smem_u32(const void* p) {
    uint32_t a;
    asm("{ .reg .u64 t; cvta.to.shared.u64 t, %1; cvt.u32.u64 %0, t; }" : "=r"(a) : "l"(p));
    return a;
}
__device__ __forceinline__ uint32_t mapa_peer(uint32_t laddr, uint32_t peer) {
    uint32_t r;
    asm("mapa.shared::cluster.u32 %0, %1, %2;" : "=r"(r) : "r"(laddr), "r"(peer));
    return r;
}
__device__ __forceinline__ void st_peer_u64(uint32_t raddr, uint64_t v) {
    asm volatile("st.shared::cluster.u64 [%0], %1;" :: "r"(raddr), "l"(v) : "memory");
}
__device__ __forceinline__ void mbar_init(uint32_t a, uint32_t cnt) {
    asm volatile("mbarrier.init.shared.b64 [%0], %1;" :: "r"(a), "r"(cnt) : "memory");
}
__device__ __forceinline__ void mbar_arrive_peer_rel(uint32_t laddr, uint32_t peer) {
    asm volatile("{\n\t.reg .b32 r;\n\t"
                 "mapa.shared::cluster.u32 r, %0, %1;\n\t"
                 "mbarrier.arrive.release.cluster.shared::cluster.b64 _, [r];\n\t}"
                 :: "r"(laddr), "r"(peer) : "memory");
}
__device__ __forceinline__ void mbar_wait_acq(uint32_t a, uint32_t parity) {
    uint32_t done;
    asm volatile("{\n\t.reg .pred p;\n\t"
                 "mbarrier.try_wait.parity.acquire.cluster.shared::cta.b64 p, [%1], %2;\n\t"
                 "selp.b32 %0, 1, 0, p;\n\t}"
                 : "=r"(done) : "r"(a), "r"(parity) : "memory");
    if (!done) {
        asm volatile("{\n\t.reg .pred P1;\n\t"
                     "WL_%=:\n\t"
                     "mbarrier.try_wait.parity.acquire.cluster.shared::cta.b64 P1, [%0], %1;\n\t"
                     "@P1 bra.uni WD_%=;\n\t"
                     "bra.uni WL_%=;\n\t"
                     "WD_%=:\n\t}"
                     :: "r"(a), "r"(parity) : "memory");
    }
}
#define CLUSTER_ARRIVE() asm volatile("barrier.cluster.arrive.aligned;" ::: "memory")
#define CLUSTER_WAIT()   asm volatile("barrier.cluster.wait.aligned;" ::: "memory")

// packed (key, idx): u64 order == (key desc, idx asc) when compared descending
__device__ __forceinline__ uint64_t pack_ki(int k, int i) {
    return ((uint64_t)(uint32_t)(k ^ 0x80000000) << 32) | (uint32_t)(~i);
}
__device__ __forceinline__ int unpack_k(uint64_t e) { return (int)((uint32_t)(e >> 32) ^ 0x80000000u); }
__device__ __forceinline__ int unpack_i(uint64_t e) { return (int)(~(uint32_t)e); }
__device__ __forceinline__ uint64_t sel4(int i, uint64_t a, uint64_t b, uint64_t c, uint64_t d) {
    return (i == 0) ? a : (i == 1) ? b : (i == 2) ? c : d;
}
// exact reference suppression: does winner (wb, wa) suppress box (cb, cab)?
__device__ __forceinline__ bool sup_test(float4 wb, float wa, float4 cb, float cab) {
    float iy1 = fmaxf(wb.x, cb.x);
    float ix1 = fmaxf(wb.y, cb.y);
    float iy2 = fminf(wb.z, cb.z);
    float ix2 = fminf(wb.w, cb.w);
    float inter = fmaxf(iy2 - iy1, 0.0f) * fmaxf(ix2 - ix1, 0.0f);
    float uni = wa + cab - inter;
    float d = fmaf(-IOU_C, uni, inter);
    return d > uni * HC;     // exact fl(inter/uni) > 0.45f
}

// ---------------- Phase 1: full-chip decode ----------------
__global__ __launch_bounds__(P1_NT)
void decode_kernel(const float* __restrict__ in)
{
    const int a = blockIdx.x * P1_NT + threadIdx.x;   // 0..9215
    const int b = blockIdx.y;
    const size_t o = (size_t)b * PADDED + a;

    if (a < ANCHORS) {
        const float* base = in + (size_t)b * (4 + NUM_CLASSES) * ANCHORS;
        float xc = base[0 * ANCHORS + a];
        float yc = base[1 * ANCHORS + a];
        float w  = base[2 * ANCHORS + a];
        float h  = base[3 * ANCHORS + a];

        float bs = base[4 * ANCHORS + a];
        int   bc = 0;
        #pragma unroll
        for (int c = 1; c < NUM_CLASSES; c++) {
            float v = base[(4 + c) * ANCHORS + a];
            if (v > bs) { bs = v; bc = c; }   // strict > = first max (jnp.argmax)
        }

        float hw = w * 0.5f;
        float hh = h * 0.5f;
        float y1 = fminf(fmaxf(yc - hh, 0.0f), 1.0f);
        float x1 = fminf(fmaxf(xc - hw, 0.0f), 1.0f);
        float y2 = fminf(fmaxf(yc + hh, 0.0f), 1.0f);
        float x2 = fminf(fmaxf(xc + hw, 0.0f), 1.0f);

        g_box[o] = make_float4(y1, x1, y2, x2);
        g_sc[o]  = (bs >= CONF) ? bs : -1.0f;
        g_cls[o] = (float)bc;
    } else {
        g_box[o] = make_float4(0.0f, 0.0f, 0.0f, 0.0f);
        g_sc[o]  = -1.0f;
        g_cls[o] = 0.0f;
    }
}

// one winner-slot IoU inside the scan (sentinel slot never suppresses)
#define SUP1(W, WA, J, CHECK)                                                  \
{   float q1 = fmaxf(W.x, ry1[k]);                                             \
    float q2 = fmaxf(W.y, rx1[k]);                                             \
    float q3 = fminf(W.z, ry2[k]);                                             \
    float q4 = fminf(W.w, rx2[k]);                                             \
    float it = fmaxf(q3 - q1, 0.0f) * fmaxf(q4 - q2, 0.0f);                    \
    float u  = WA + ab - it;                                                   \
    float e  = fmaf(-IOU_C, u, it);                                            \
    bool s = (e > u * HC);                                                     \
    if (CHECK) s = s || (gg == J);                                             \
    sup = sup || s;                                                            \
}

// suppression by 4 winner slots + fresh per-thread top-4
#define SCAN4(CHECK)                                                           \
{                                                                              \
    int nk0=NEG_INF_I, nj0=IDX_SENT, nk1=NEG_INF_I, nj1=IDX_SENT;              \
    int nk2=NEG_INF_I, nj2=IDX_SENT, nk3=NEG_INF_I, nj3=IDX_SENT;              \
    _Pragma("unroll")                                                          \
    for (int k = 0; k < KPT; k++) {                                            \
        float v = rsc[k];                                                      \
        float ab = rab[k];                                                     \
        int gg = gbase + k;                                                    \
        bool sup = false;                                                      \
        SUP1(W0, WA0, J0, CHECK)                                               \
        SUP1(W1, WA1, J1, CHECK)                                               \
        SUP1(W2, WA2, J2, CHECK)                                               \
        SUP1(W3, WA3, J3, CHECK)                                               \
        v = sup ? -1.0f : v;                                                   \
        rsc[k] = v;                                                            \
        int ik = __float_as_int(v);                                            \
        if (ik > nk0)      { nk3=nk2;nj3=nj2; nk2=nk1;nj2=nj1;                 \
                             nk1=nk0;nj1=nj0; nk0=ik;nj0=gg; }                 \
        else if (ik > nk1) { nk3=nk2;nj3=nj2; nk2=nk1;nj2=nj1; nk1=ik;nj1=gg; }\
        else if (ik > nk2) { nk3=nk2;nj3=nj2; nk2=ik;nj2=gg; }                 \
        else if (ik > nk3) { nk3=ik;nj3=gg; }                                  \
    }                                                                          \
    tk0=nk0;ti0=nj0; tk1=nk1;ti1=nj1; tk2=nk2;ti2=nj2; tk3=nk3;ti3=nj3;        \
}

// ---------------- Phase 2: 2-CTA-cluster NMS, top-4 multi-emit ----------------
__global__ __launch_bounds__(NT, 1) __cluster_dims__(2, 1, 1)
void nms_kernel(float* __restrict__ out)
{
    extern __shared__ char smem[];
    float4* sbox = reinterpret_cast<float4*>(smem);                 // FULL boxes
    float*  scls = reinterpret_cast<float*>(smem + PADDED * 16);    // FULL classes

    __shared__ int red_k[2][64];             // double-buffered warp top-4 (48 used + 16 pad)
    __shared__ int red_i[2][64];
    __shared__ __align__(32) uint64_t s_mail[2][4];   // peer-written CTA top-4 (packed)
    __shared__ uint64_t s_mbar[2];

    const int tid  = threadIdx.x;
    const int lane = tid & 31;
    const int wid  = tid >> 5;
    const unsigned FULL = 0xffffffffu;
    uint32_t rank;
    asm("mov.u32 %0, %%cluster_ctarank;" : "=r"(rank));
    const uint32_t peer = rank ^ 1;
    const int b = blockIdx.x >> 1;

    const uint32_t mb0   = smem_u32(&s_mbar[0]);
    const uint32_t mb1   = smem_u32(&s_mbar[1]);
    const uint32_t mail0 = smem_u32(&s_mail[0][0]);
    const uint32_t mail1 = smem_u32(&s_mail[1][0]);

    if (tid == 0) { mbar_init(mb0, 1); mbar_init(mb1, 1); }
    if (tid < 16) {                           // pad slots 48..63 (both parities, written once)
        red_k[0][48 + tid] = NEG_INF_I; red_i[0][48 + tid] = IDX_SENT;
        red_k[1][48 + tid] = NEG_INF_I; red_i[1][48 + tid] = IDX_SENT;
    }

    // coalesced fill of the FULL arrays (both CTAs replicate)
    const float4* gb = g_box + (size_t)b * PADDED;
    const float*  gc = g_cls + (size_t)b * PADDED;
    for (int a = tid; a < PADDED; a += NT) { sbox[a] = gb[a]; scls[a] = gc[a]; }
    __syncthreads();

    CLUSTER_ARRIVE(); CLUSTER_WAIT();         // mbarrier init visible cluster-wide

    // register slice: this CTA owns global anchors [rank*HALF + t*KPT, +KPT)
    float ry1[KPT], rx1[KPT], ry2[KPT], rx2[KPT], rsc[KPT], rab[KPT];
    const int gbase = (int)rank * HALF + tid * KPT;
    const float* gs = g_sc + (size_t)b * PADDED + gbase;
    int tk0=NEG_INF_I, ti0=IDX_SENT, tk1=NEG_INF_I, ti1=IDX_SENT;
    int tk2=NEG_INF_I, ti2=IDX_SENT, tk3=NEG_INF_I, ti3=IDX_SENT;
    #pragma unroll
    for (int k = 0; k < KPT; k++) {
        float4 v = sbox[gbase + k];
        ry1[k] = v.x; rx1[k] = v.y; ry2[k] = v.z; rx2[k] = v.w;
        rab[k] = (v.z - v.x) * (v.w - v.y);
        float sv = gs[k];
        rsc[k] = sv;
        int ik = __float_as_int(sv);
        int gg = gbase + k;
        if (ik > tk0)      { tk3=tk2;ti3=ti2; tk2=tk1;ti2=ti1;
                             tk1=tk0;ti1=ti0; tk0=ik;ti0=gg; }
        else if (ik > tk1) { tk3=tk2;ti3=ti2; tk2=tk1;ti2=ti1; tk1=ik;ti1=gg; }
        else if (ik > tk2) { tk3=tk2;ti3=ti2; tk2=ik;ti2=gg; }
        else if (ik > tk3) { tk3=ik;ti3=gg; }
    }

    float* out_boxes = out + (size_t)b * MAX_DET * 4;
    float* out_cls   = out + (size_t)BATCH * MAX_DET * 4 + (size_t)b * MAX_DET;
    float* out_sc    = out + (size_t)BATCH * MAX_DET * 5 + (size_t)b * MAX_DET;
    float* out_nd    = out + (size_t)BATCH * MAX_DET * 6 + b;

    int ndet = 0, p = 0, ph0 = 0, ph1 = 0;
    while (ndet < MAX_DET) {
        // ---- Stage B: warp top-4 (4 pop rounds; lane order == idx order) ----
        {
            int a0=tk0, e0i=ti0, a1=tk1, e1i=ti1, a2=tk2, e2i=ti2, a3=tk3, e3i=ti3;
            #pragma unroll
            for (int r = 0; r < 4; r++) {
                int m = __reduce_max_sync(FULL, a0);
                unsigned ball = __ballot_sync(FULL, a0 == m);
                int src = __ffs(ball) - 1;
                int wi = __shfl_sync(FULL, e0i, src);
                if (lane == 0) { red_k[p][wid * 4 + r] = m; red_i[p][wid * 4 + r] = wi; }
                if (lane == src) { a0=a1;e0i=e1i; a1=a2;e1i=e2i; a2=a3;e2i=e3i;
                                   a3=NEG_INF_I; e3i=IDX_SENT; }
            }
        }
        __syncthreads();

        // ---- Stage C: CTA top-4 over 64 slots, exact idx tie-break ----
        int ck0, ci0, ck1, ci1, ck2, ci2, ck3, ci3;
        {
            int ka = red_k[p][lane],      ia = red_i[p][lane];
            int kb = red_k[p][lane + 32], ib = red_i[p][lane + 32];
            uint64_t ea = pack_ki(ka, ia), eb = pack_ki(kb, ib);
            uint64_t fr = (ea > eb) ? ea : eb;
            uint64_t se = (ea > eb) ? eb : ea;
            #define CROUND(CK, CI)                                             \
            {   int fk = unpack_k(fr); int fi = unpack_i(fr);                  \
                int M = __reduce_max_sync(FULL, fk);                           \
                unsigned c = (fk == M) ? (unsigned)fi : 0xFFFFFFFFu;           \
                unsigned I = __reduce_min_sync(FULL, c);                       \
                CK = M; CI = (int)I;                                           \
                if (fk == M && (unsigned)fi == I) {                            \
                    fr = se; se = pack_ki(NEG_INF_I, IDX_SENT); }              \
            }
            CROUND(ck0, ci0) CROUND(ck1, ci1) CROUND(ck2, ci2) CROUND(ck3, ci3)
            #undef CROUND
        }
        uint64_t o0 = pack_ki(ck0, ci0), o1 = pack_ki(ck1, ci1);
        uint64_t o2 = pack_ki(ck2, ci2), o3 = pack_ki(ck3, ci3);

        // ---- Stage D: exchange packed CTA top-4 with peer ----
        // Parity double-buffer: rewriting peer mail[p] at pass t is safe since our
        // pass t-1 wait on mbar[p^1] required the peer's arrive, program-ordered
        // after the peer's pass t-2 reads of mail[p].
        uint32_t mail = p ? mail1 : mail0;
        uint32_t mb   = p ? mb1   : mb0;
        if (tid == 0) {
            uint32_t r = mapa_peer(mail, peer);
            st_peer_u64(r +  0, o0);
            st_peer_u64(r +  8, o1);
            st_peer_u64(r + 16, o2);
            st_peer_u64(r + 24, o3);
            mbar_arrive_peer_rel(mb, peer);
        }
        mbar_wait_acq(mb, (uint32_t)(p ? ph1 : ph0));
        if (p) ph1 ^= 1; else ph0 ^= 1;

        // ---- Stage E: merge two sorted 4-lists (symmetric in both CTAs) ----
        uint64_t q0 = s_mail[p][0], q1 = s_mail[p][1], q2 = s_mail[p][2], q3 = s_mail[p][3];
        uint64_t e0, e1, e2, e3;
        {
            int ai = 0, bi = 0;
            #define TAKE(dst)                                                  \
            {   uint64_t ov = (ai > 3) ? 0ull : sel4(ai, o0, o1, o2, o3);      \
                uint64_t pv = (bi > 3) ? 0ull : sel4(bi, q0, q1, q2, q3);      \
                bool ow = ov > pv; dst = ow ? ov : pv;                         \
                if (ow) ai++; else bi++; }
            TAKE(e0) TAKE(e1) TAKE(e2) TAKE(e3)
            #undef TAKE
        }
        int mk0 = unpack_k(e0), mi0 = unpack_i(e0);
        int mk1 = unpack_k(e1), mi1 = unpack_i(e1);
        int mk2 = unpack_k(e2), mi2 = unpack_i(e2);
        int mk3 = unpack_k(e3), mi3 = unpack_i(e3);

        if (mk0 < 0) break;                   // symmetric data -> uniform break

        bool v1 = mk1 > 0, v2 = mk2 > 0, v3 = mk3 > 0;
        float4 cb0 = sbox[mi0];
        float4 cb1 = sbox[v1 ? mi1 : 0];
        float4 cb2 = sbox[v2 ? mi2 : 0];
        float4 cb3 = sbox[v3 ? mi3 : 0];
        float ca0 = (cb0.z - cb0.x) * (cb0.w - cb0.y);
        float ca1 = (cb1.z - cb1.x) * (cb1.w - cb1.y);
        float ca2 = (cb2.z - cb2.x) * (cb2.w - cb2.y);
        float ca3 = (cb3.z - cb3.x) * (cb3.w - cb3.y);

        // ---- survivorship chain (uniform; exact reference tests) ----
        bool s10 = sup_test(cb0, ca0, cb1, ca1);
        bool s20 = sup_test(cb0, ca0, cb2, ca2);
        bool s21 = sup_test(cb1, ca1, cb2, ca2);
        bool s30 = sup_test(cb0, ca0, cb3, ca3);
        bool s31 = sup_test(cb1, ca1, cb3, ca3);
        bool s32 = sup_test(cb2, ca2, cb3, ca3);

        int budget = MAX_DET - ndet;          // >= 1
        bool conf1 = v1 && (1 < budget) && !s10;
        int  cnt2  = 1 + (conf1 ? 1 : 0);
        bool conf2 = v2 && (cnt2 < budget) && !s20 && !(conf1 && s21);
        int  cnt3  = cnt2 + (conf2 ? 1 : 0);
        bool conf3 = v3 && (cnt3 < budget) && !s30 && !(conf1 && s31) && !(conf2 && s32);
        int  nw    = cnt3 + (conf3 ? 1 : 0);

        if (rank == 0 && tid == 0) {
            out_boxes[ndet * 4 + 0] = cb0.x;
            out_boxes[ndet * 4 + 1] = cb0.y;
            out_boxes[ndet * 4 + 2] = cb0.z;
            out_boxes[ndet * 4 + 3] = cb0.w;
            out_cls[ndet] = scls[mi0];
            out_sc[ndet]  = __int_as_float(mk0);
            if (conf1) {
                int q = ndet + 1;
                out_boxes[q * 4 + 0] = cb1.x; out_boxes[q * 4 + 1] = cb1.y;
                out_boxes[q * 4 + 2] = cb1.z; out_boxes[q * 4 + 3] = cb1.w;
                out_cls[q] = scls[mi1]; out_sc[q] = __int_as_float(mk1);
            }
            if (conf2) {
                int q = ndet + cnt2;
                out_boxes[q * 4 + 0] = cb2.x; out_boxes[q * 4 + 1] = cb2.y;
                out_boxes[q * 4 + 2] = cb2.z; out_boxes[q * 4 + 3] = cb2.w;
                out_cls[q] = scls[mi2]; out_sc[q] = __int_as_float(mk2);
            }
            if (conf3) {
                int q = ndet + cnt3;
                out_boxes[q * 4 + 0] = cb3.x; out_boxes[q * 4 + 1] = cb3.y;
                out_boxes[q * 4 + 2] = cb3.z; out_boxes[q * 4 + 3] = cb3.w;
                out_cls[q] = scls[mi3]; out_sc[q] = __int_as_float(mk3);
            }
        }

        // ---- winner slots: unconfirmed -> sentinel box (never suppresses) ----
        float4 W0 = cb0;                       float WA0 = ca0; int J0 = mi0;
        float4 W1 = conf1 ? cb1 : make_float4(-2.f, -2.f, -2.f, -2.f);
        float  WA1 = conf1 ? ca1 : 0.0f;       int J1 = conf1 ? mi1 : -1;
        float4 W2 = conf2 ? cb2 : make_float4(-2.f, -2.f, -2.f, -2.f);
        float  WA2 = conf2 ? ca2 : 0.0f;       int J2 = conf2 ? mi2 : -1;
        float4 W3 = conf3 ? cb3 : make_float4(-2.f, -2.f, -2.f, -2.f);
        float  WA3 = conf3 ? ca3 : 0.0f;       int J3 = conf3 ? mi3 : -1;

        ndet += nw;

        // Fast path: positive-area confirmed winners self-suppress via their own
        // IoU test (in == ab == aa exactly => e = 0.55*aa > aa*2^-26).
        bool bothpos = (ca0 > 0.0f) && (!conf1 || ca1 > 0.0f)
                    && (!conf2 || ca2 > 0.0f) && (!conf3 || ca3 > 0.0f);  // uniform
        if (ndet < MAX_DET && tk0 > 0) {       // dead slice -> state stays exact
            if (bothpos) SCAN4(0) else SCAN4(1)
        }

        p ^= 1;
    }

    // tail zero-fill (out is poisoned; reference emits zeros for !ok slots)
    if (rank == 0) {
        for (int i = ndet + tid; i < MAX_DET; i += NT) {
            out_boxes[i * 4 + 0] = 0.0f;
            out_boxes[i * 4 + 1] = 0.0f;
            out_boxes[i * 4 + 2] = 0.0f;
            out_boxes[i * 4 + 3] = 0.0f;
            out_cls[i] = 0.0f;
            out_sc[i]  = 0.0f;
        }
        if (tid == 0) *out_nd = (float)ndet;
    }

    CLUSTER_ARRIVE(); CLUSTER_WAIT();    // no CTA exits while peer may signal it
}

extern "C" void kernel_launch(void* const* d_in, const int* in_sizes, int n_in,
                              void* d_out, int out_size)
{
    (void)in_sizes; (void)n_in; (void)out_size;
    const float* in = (const float*)d_in[0];
    float* out = (float*)d_out;

    cudaFuncSetAttribute(nms_kernel,
                         cudaFuncAttributeMaxDynamicSharedMemorySize, SMEM_BYTES);

    dim3 g1(P1_GRIDX, BATCH);
    decode_kernel<<<g1, P1_NT>>>(in);
    nms_kernel<<<2 * BATCH, NT, SMEM_BYTES>>>(out);
}

// round 10
// speedup vs baseline: 1.0689x; 1.0689x over previous
#include <cuda_runtime.h>
#include <cstdint>

#define NUM_CLASSES 32
#define MAX_DET     100
#define CONF        0.25f
#define IOU_C       0.45f
#define HC          1.4901161193847656e-8f   // 2^-26 = half-ulp(0.45f)
#define BATCH       64
#define ANCHORS     8400
#define NT          512
#define KPT         9
#define HALF        (NT * KPT)               // 4608 anchors per CTA
#define PADDED      (2 * HALF)               // 9216
#define NWARPS      (NT / 32)                // 16
#define NEG_INF_I   ((int)0x80000000)
#define IDX_SENT    0x7FFFFFFF

#define P1_NT       512
#define P1_GRIDX    (PADDED / P1_NT)         // 18

// scratch (allocation-free rule: __device__ globals)
__device__ float4 g_box[BATCH * PADDED];
__device__ float  g_sc [BATCH * PADDED];
__device__ float  g_cls[BATCH * PADDED];

// NMS dynamic smem per CTA: FULL float4 boxes[9216] | FULL float cls[9216]
#define SMEM_BYTES (PADDED * 16 + PADDED * 4)

// ---------------- helpers ----------------
__device__ __forceinline__ uint32_t smem_u32(const void* p) {
    uint32_t a;
    asm("{ .reg .u64 t; cvta.to.shared.u64 t, %1; cvt.u32.u64 %0, t; }" : "=r"(a) : "l"(p));
    return a;
}
__device__ __forceinline__ uint32_t mapa_peer(uint32_t laddr, uint32_t peer) {
    uint32_t r;
    asm("mapa.shared::cluster.u32 %0, %1, %2;" : "=r"(r) : "r"(laddr), "r"(peer));
    return r;
}
__device__ __forceinline__ void st_peer_u64(uint32_t raddr, uint64_t v) {
    asm volatile("st.shared::cluster.u64 [%0], %1;" :: "r"(raddr), "l"(v) : "memory");
}
__device__ __forceinline__ void mbar_init(uint32_t a, uint32_t cnt) {
    asm volatile("mbarrier.init.shared.b64 [%0], %1;" :: "r"(a), "r"(cnt) : "memory");
}
__device__ __forceinline__ void mbar_arrive_peer_rel(uint32_t laddr, uint32_t peer) {
    asm volatile("{\n\t.reg .b32 r;\n\t"
                 "mapa.shared::cluster.u32 r, %0, %1;\n\t"
                 "mbarrier.arrive.release.cluster.shared::cluster.b64 _, [r];\n\t}"
                 :: "r"(laddr), "r"(peer) : "memory");
}
__device__ __forceinline__ void mbar_wait_acq(uint32_t a, uint32_t parity) {
    uint32_t done;
    asm volatile("{\n\t.reg .pred p;\n\t"
                 "mbarrier.try_wait.parity.acquire.cluster.shared::cta.b64 p, [%1], %2;\n\t"
                 "selp.b32 %0, 1, 0, p;\n\t}"
                 : "=r"(done) : "r"(a), "r"(parity) : "memory");
    if (!done) {
        asm volatile("{\n\t.reg .pred P1;\n\t"
                     "WL_%=:\n\t"
                     "mbarrier.try_wait.parity.acquire.cluster.shared::cta.b64 P1, [%0], %1;\n\t"
                     "@P1 bra.uni WD_%=;\n\t"
                     "bra.uni WL_%=;\n\t"
                     "WD_%=:\n\t}"
                     :: "r"(a), "r"(parity) : "memory");
    }
}
#define CLUSTER_ARRIVE() asm volatile("barrier.cluster.arrive.aligned;" ::: "memory")
#define CLUSTER_WAIT()   asm volatile("barrier.cluster.wait.aligned;" ::: "memory")

// packed (key, idx): u64 descending order == (key desc, idx asc)
__device__ __forceinline__ uint64_t pack_ki(int k, int i) {
    return ((uint64_t)(uint32_t)(k ^ 0x80000000) << 32) | (uint32_t)(~i);
}
__device__ __forceinline__ int unpack_k(uint64_t e) { return (int)((uint32_t)(e >> 32) ^ 0x80000000u); }
__device__ __forceinline__ int unpack_i(uint64_t e) { return (int)(~(uint32_t)e); }

// exact reference suppression: does winner (wb, wa) suppress box (cb, cab)?
__device__ __forceinline__ bool sup_test(float4 wb, float wa, float4 cb, float cab) {
    float iy1 = fmaxf(wb.x, cb.x);
    float ix1 = fmaxf(wb.y, cb.y);
    float iy2 = fminf(wb.z, cb.z);
    float ix2 = fminf(wb.w, cb.w);
    float inter = fmaxf(iy2 - iy1, 0.0f) * fmaxf(ix2 - ix1, 0.0f);
    float uni = wa + cab - inter;
    float d = fmaf(-IOU_C, uni, inter);
    return d > uni * HC;     // exact fl(inter/uni) > 0.45f
}

// ---------------- Phase 1: full-chip decode ----------------
__global__ __launch_bounds__(P1_NT)
void decode_kernel(const float* __restrict__ in)
{
    const int a = blockIdx.x * P1_NT + threadIdx.x;   // 0..9215
    const int b = blockIdx.y;
    const size_t o = (size_t)b * PADDED + a;

    if (a < ANCHORS) {
        const float* base = in + (size_t)b * (4 + NUM_CLASSES) * ANCHORS;
        float xc = base[0 * ANCHORS + a];
        float yc = base[1 * ANCHORS + a];
        float w  = base[2 * ANCHORS + a];
        float h  = base[3 * ANCHORS + a];

        float bs = base[4 * ANCHORS + a];
        int   bc = 0;
        #pragma unroll
        for (int c = 1; c < NUM_CLASSES; c++) {
            float v = base[(4 + c) * ANCHORS + a];
            if (v > bs) { bs = v; bc = c; }   // strict > = first max (jnp.argmax)
        }

        float hw = w * 0.5f;
        float hh = h * 0.5f;
        float y1 = fminf(fmaxf(yc - hh, 0.0f), 1.0f);
        float x1 = fminf(fmaxf(xc - hw, 0.0f), 1.0f);
        float y2 = fminf(fmaxf(yc + hh, 0.0f), 1.0f);
        float x2 = fminf(fmaxf(xc + hw, 0.0f), 1.0f);

        g_box[o] = make_float4(y1, x1, y2, x2);
        g_sc[o]  = (bs >= CONF) ? bs : -1.0f;
        g_cls[o] = (float)bc;
    } else {
        g_box[o] = make_float4(0.0f, 0.0f, 0.0f, 0.0f);
        g_sc[o]  = -1.0f;
        g_cls[o] = 0.0f;
    }
}

// one winner-slot IoU inside the scan (sentinel slot never suppresses)
#define SUP1(W, WA, J, CHECK)                                                  \
{   float q1 = fmaxf(W.x, ry1[k]);                                             \
    float q2 = fmaxf(W.y, rx1[k]);                                             \
    float q3 = fminf(W.z, ry2[k]);                                             \
    float q4 = fminf(W.w, rx2[k]);                                             \
    float it = fmaxf(q3 - q1, 0.0f) * fmaxf(q4 - q2, 0.0f);                    \
    float u  = WA + ab - it;                                                   \
    float e  = fmaf(-IOU_C, u, it);                                            \
    bool s = (e > u * HC);                                                     \
    if (CHECK) s = s || (gg == J);                                             \
    sup = sup || s;                                                            \
}

// suppression by 2 (or 3) winner slots + fresh per-thread top-2
#define SCAN_BODY(THREE, CHECK)                                                \
{                                                                              \
    int nk1 = NEG_INF_I, ni1 = 0, nk2 = NEG_INF_I, ni2 = 0;                    \
    _Pragma("unroll")                                                          \
    for (int k = 0; k < KPT; k++) {                                            \
        float v = rsc[k];                                                      \
        float ab = (ry2[k] - ry1[k]) * (rx2[k] - rx1[k]);                      \
        int gg = gbase + k;                                                    \
        bool sup = false;                                                      \
        SUP1(W0, WA0, J0, CHECK)                                               \
        SUP1(W1, WA1, J1, CHECK)                                               \
        if (THREE) { SUP1(W2, WA2, J2, CHECK) }                                \
        v = sup ? -1.0f : v;                                                   \
        rsc[k] = v;                                                            \
        int ik = __float_as_int(v);                                            \
        if (ik > nk1)      { nk2 = nk1; ni2 = ni1; nk1 = ik; ni1 = gg; }       \
        else if (ik > nk2) { nk2 = ik; ni2 = gg; }                             \
    }                                                                          \
    tk1 = nk1; ti1 = ni1; tk2 = nk2; ti2 = ni2;                                \
}

// ---------------- Phase 2: 2-CTA-cluster NMS, opportunistic top-3 ----------------
__global__ __launch_bounds__(NT, 1) __cluster_dims__(2, 1, 1)
void nms_kernel(float* __restrict__ out)
{
    extern __shared__ char smem[];
    float4* sbox = reinterpret_cast<float4*>(smem);                 // FULL boxes
    float*  scls = reinterpret_cast<float*>(smem + PADDED * 16);    // FULL classes

    __shared__ int red_k[2][2 * NWARPS];     // double-buffered warp top-2 (32 entries)
    __shared__ int red_i[2][2 * NWARPS];
    __shared__ __align__(16) uint64_t s_mail[2][2];   // peer-written CTA top-2 (packed)
    __shared__ uint64_t s_mbar[2];

    const int tid  = threadIdx.x;
    const int lane = tid & 31;
    const int wid  = tid >> 5;
    const unsigned FULL = 0xffffffffu;
    uint32_t rank;
    asm("mov.u32 %0, %%cluster_ctarank;" : "=r"(rank));
    const uint32_t peer = rank ^ 1;
    const int b = blockIdx.x >> 1;

    const uint32_t mb0 = smem_u32(&s_mbar[0]);
    const uint32_t mb1 = smem_u32(&s_mbar[1]);
    // peer mailbox addresses hoisted out of the loop
    const uint32_t pm0 = mapa_peer(smem_u32(&s_mail[0][0]), peer);
    const uint32_t pm1 = mapa_peer(smem_u32(&s_mail[1][0]), peer);

    if (tid == 0) { mbar_init(mb0, 1); mbar_init(mb1, 1); }

    // coalesced fill of the FULL arrays (both CTAs replicate)
    const float4* gb = g_box + (size_t)b * PADDED;
    const float*  gc = g_cls + (size_t)b * PADDED;
    for (int a = tid; a < PADDED; a += NT) { sbox[a] = gb[a]; scls[a] = gc[a]; }
    __syncthreads();

    CLUSTER_ARRIVE(); CLUSTER_WAIT();        // mbarrier init visible cluster-wide

    // register slice: this CTA owns global anchors [rank*HALF + t*9, +9)
    float ry1[KPT], rx1[KPT], ry2[KPT], rx2[KPT], rsc[KPT];
    const int gbase = (int)rank * HALF + tid * KPT;
    const float* gs = g_sc + (size_t)b * PADDED + gbase;
    int tk1 = NEG_INF_I, ti1 = 0, tk2 = NEG_INF_I, ti2 = 0;
    #pragma unroll
    for (int k = 0; k < KPT; k++) {
        float4 v = sbox[gbase + k];
        ry1[k] = v.x; rx1[k] = v.y; ry2[k] = v.z; rx2[k] = v.w;
        float sv = gs[k];
        rsc[k] = sv;
        int ik = __float_as_int(sv);
        if (ik > tk1)      { tk2 = tk1; ti2 = ti1; tk1 = ik; ti1 = gbase + k; }
        else if (ik > tk2) { tk2 = ik; ti2 = gbase + k; }
    }

    float* out_boxes = out + (size_t)b * MAX_DET * 4;
    float* out_cls   = out + (size_t)BATCH * MAX_DET * 4 + (size_t)b * MAX_DET;
    float* out_sc    = out + (size_t)BATCH * MAX_DET * 5 + (size_t)b * MAX_DET;
    float* out_nd    = out + (size_t)BATCH * MAX_DET * 6 + b;

    const uint64_t SENTMIN = pack_ki(NEG_INF_I, IDX_SENT);

    int ndet = 0, p = 0, ph0 = 0, ph1 = 0;
    while (ndet < MAX_DET) {
        // ---- Stage B: warp top-2 (redux + ballot; lane order == idx order) ----
        int m1 = __reduce_max_sync(FULL, tk1);
        unsigned ball = __ballot_sync(FULL, tk1 == m1);
        int src = __ffs(ball) - 1;
        int wi1 = __shfl_sync(FULL, ti1, src);
        int kx = (lane == src) ? tk2 : tk1;
        int ix = (lane == src) ? ti2 : ti1;
        int m2w = __reduce_max_sync(FULL, kx);
        ball = __ballot_sync(FULL, kx == m2w);
        src  = __ffs(ball) - 1;
        int wi2 = __shfl_sync(FULL, ix, src);
        if (lane == 0) {
            red_k[p][2 * wid]     = m1;  red_i[p][2 * wid]     = wi1;
            red_k[p][2 * wid + 1] = m2w; red_i[p][2 * wid + 1] = wi2;
        }
        __syncthreads();

        // ---- Stage C: CTA top-2 over 32 entries (every warp, redundantly) ----
        int ek = red_k[p][lane];
        int ei = red_i[p][lane];
        int cm1 = __reduce_max_sync(FULL, ek);
        ball = __ballot_sync(FULL, ek == cm1);
        src  = __ffs(ball) - 1;
        int cg1 = __shfl_sync(FULL, ei, src);
        int ekx = (lane == src) ? NEG_INF_I : ek;
        int cm2 = __reduce_max_sync(FULL, ekx);
        ball = __ballot_sync(FULL, ekx == cm2);
        int src2 = __ffs(ball) - 1;
        int cg2 = __shfl_sync(FULL, ei, src2);

        // ---- Stage D: exchange packed CTA top-2 with peer ----
        // Parity double-buffer: rewriting peer mail[p] at pass t is safe since our
        // pass t-1 wait on mbar[p^1] required the peer's arrive, program-ordered
        // after the peer's pass t-2 reads of mail[p].
        uint64_t a0p = pack_ki(cm1, cg1);
        uint64_t a1p = pack_ki(cm2, cg2);
        uint32_t mb  = p ? mb1 : mb0;
        if (tid == 0) {
            uint32_t r = p ? pm1 : pm0;
            st_peer_u64(r + 0, a0p);
            st_peer_u64(r + 8, a1p);
            mbar_arrive_peer_rel(mb, peer);
        }
        mbar_wait_acq(mb, (uint32_t)(p ? ph1 : ph0));
        if (p) ph1 ^= 1; else ph0 ^= 1;

        // ---- Stage E: merge own pair with peer pair; opportunistic 3rd ----
        uint64_t b0p = s_mail[p][0], b1p = s_mail[p][1];
        bool w0 = a0p > b0p;
        uint64_t e0 = w0 ? a0p : b0p;
        uint64_t xa = w0 ? a1p : a0p;        // own head after take 1
        uint64_t xb = w0 ? b0p : b1p;        // peer head after take 1
        bool w1 = xa > xb;
        uint64_t e1 = w1 ? xa : xb;
        uint64_t ya = w1 ? (w0 ? SENTMIN : a1p) : xa;
        uint64_t yb = w1 ? xb : (w0 ? b1p : SENTMIN);
        uint64_t e2 = (ya > yb) ? ya : yb;
        bool trust3 = (w0 != w1);            // merged #1,#2 from different CTAs
                                             // => e2 is the exact global #3

        int mk0 = unpack_k(e0), mi0 = unpack_i(e0);
        int mk1 = unpack_k(e1), mi1 = unpack_i(e1);
        int mk2 = unpack_k(e2), mi2 = unpack_i(e2);

        if (mk0 < 0) break;                  // symmetric data -> uniform break

        bool v1 = mk1 > 0;
        bool v2 = (mk2 > 0) && trust3;
        float4 cb0 = sbox[mi0];
        float4 cb1 = sbox[v1 ? mi1 : 0];
        float4 cb2 = sbox[v2 ? mi2 : 0];
        float ca0 = (cb0.z - cb0.x) * (cb0.w - cb0.y);
        float ca1 = (cb1.z - cb1.x) * (cb1.w - cb1.y);
        float ca2 = (cb2.z - cb2.x) * (cb2.w - cb2.y);

        // ---- survivorship chain (uniform; exact reference tests) ----
        bool s10 = sup_test(cb0, ca0, cb1, ca1);
        bool s20 = sup_test(cb0, ca0, cb2, ca2);
        bool s21 = sup_test(cb1, ca1, cb2, ca2);

        int budget = MAX_DET - ndet;         // >= 1
        bool conf1 = v1 && (budget > 1) && !s10;
        int  cnt2  = 1 + (conf1 ? 1 : 0);
        bool conf2 = v2 && (cnt2 < budget) && !s20 && !(conf1 && s21);
        int  nw    = cnt2 + (conf2 ? 1 : 0);

        if (rank == 0 && tid == 0) {
            out_boxes[ndet * 4 + 0] = cb0.x;
            out_boxes[ndet * 4 + 1] = cb0.y;
            out_boxes[ndet * 4 + 2] = cb0.z;
            out_boxes[ndet * 4 + 3] = cb0.w;
            out_cls[ndet] = scls[mi0];
            out_sc[ndet]  = __int_as_float(mk0);
            if (conf1) {
                int q = ndet + 1;
                out_boxes[q * 4 + 0] = cb1.x; out_boxes[q * 4 + 1] = cb1.y;
                out_boxes[q * 4 + 2] = cb1.z; out_boxes[q * 4 + 3] = cb1.w;
                out_cls[q] = scls[mi1]; out_sc[q] = __int_as_float(mk1);
            }
            if (conf2) {
                int q = ndet + cnt2;
                out_boxes[q * 4 + 0] = cb2.x; out_boxes[q * 4 + 1] = cb2.y;
                out_boxes[q * 4 + 2] = cb2.z; out_boxes[q * 4 + 3] = cb2.w;
                out_cls[q] = scls[mi2]; out_sc[q] = __int_as_float(mk2);
            }
        }

        // ---- winner slots: unconfirmed -> sentinel box (never suppresses) ----
        float4 W0 = cb0;                      float WA0 = ca0; int J0 = mi0;
        float4 W1 = conf1 ? cb1 : make_float4(-2.f, -2.f, -2.f, -2.f);
        float  WA1 = conf1 ? ca1 : 0.0f;      int J1 = conf1 ? mi1 : -1;
        float4 W2 = cb2;                      float WA2 = ca2; int J2 = mi2;   // only read if conf2

        ndet += nw;

        // Fast path: positive-area confirmed winners self-suppress via their own
        // IoU test (in == ab == aa exactly => e = 0.55*aa > aa*2^-26).
        bool bothpos = (ca0 > 0.0f) && (!conf1 || ca1 > 0.0f)
                    && (!conf2 || ca2 > 0.0f);                 // uniform
        if (ndet < MAX_DET && tk1 > 0) {      // dead slice -> state stays exact
            if (conf2) { if (bothpos) SCAN_BODY(1, 0) else SCAN_BODY(1, 1) }
            else       { if (bothpos) SCAN_BODY(0, 0) else SCAN_BODY(0, 1) }
        }

        p ^= 1;
    }

    // tail zero-fill (out is poisoned; reference emits zeros for !ok slots)
    if (rank == 0) {
        for (int i = ndet + tid; i < MAX_DET; i += NT) {
            out_boxes[i * 4 + 0] = 0.0f;
            out_boxes[i * 4 + 1] = 0.0f;
            out_boxes[i * 4 + 2] = 0.0f;
            out_boxes[i * 4 + 3] = 0.0f;
            out_cls[i] = 0.0f;
            out_sc[i]  = 0.0f;
        }
        if (tid == 0) *out_nd = (float)ndet;
    }

    CLUSTER_ARRIVE(); CLUSTER_WAIT();    // no CTA exits while peer may signal it
}

extern "C" void kernel_launch(void* const* d_in, const int* in_sizes, int n_in,
                              void* d_out, int out_size)
{
    (void)in_sizes; (void)n_in; (void)out_size;
    const float* in = (const float*)d_in[0];
    float* out = (float*)d_out;

    cudaFuncSetAttribute(nms_kernel,
                         cudaFuncAttributeMaxDynamicSharedMemorySize, SMEM_BYTES);

    dim3 g1(P1_GRIDX, BATCH);
    decode_kernel<<<g1, P1_NT>>>(in);
    nms_kernel<<<2 * BATCH, NT, SMEM_BYTES>>>(out);
}

// round 11
// speedup vs baseline: 1.2359x; 1.1562x over previous
#include <cuda_runtime.h>
#include <cstdint>

#define NUM_CLASSES 32
#define MAX_DET     100
#define CONF        0.25f
#define IOU_C       0.45f
#define HC          1.4901161193847656e-8f   // 2^-26 = half-ulp(0.45f)
#define BATCH       64
#define ANCHORS     8400
#define NT          512
#define KPT         9
#define HALF        (NT * KPT)               // 4608 anchors per CTA
#define PADDED      (2 * HALF)               // 9216
#define NWARPS      (NT / 32)                // 16
#define GROUPW      (32 * KPT)               // 288 anchors per warp-group
#define NEG_INF_I   ((int)0x80000000)
#define IDX_SENT    0x7FFFFFFF

#define P1_NT       512
#define P1_GRIDX    (PADDED / P1_NT)         // 18

// scratch (allocation-free rule: __device__ globals)
__device__ float4 g_box[BATCH * PADDED];
__device__ float  g_sc [BATCH * PADDED];
__device__ float  g_cls[BATCH * PADDED];

// NMS dynamic smem per CTA: FULL float4 boxes[9216] | FULL float cls[9216]
#define SMEM_BYTES (PADDED * 16 + PADDED * 4)

// ---------------- helpers ----------------
__device__ __forceinline__ uint32_t smem_u32(const void* p) {
    uint32_t a;
    asm("{ .reg .u64 t; cvta.to.shared.u64 t, %1; cvt.u32.u64 %0, t; }" : "=r"(a) : "l"(p));
    return a;
}
__device__ __forceinline__ uint32_t mapa_peer(uint32_t laddr, uint32_t peer) {
    uint32_t r;
    asm("mapa.shared::cluster.u32 %0, %1, %2;" : "=r"(r) : "r"(laddr), "r"(peer));
    return r;
}
__device__ __forceinline__ void st_peer_u64(uint32_t raddr, uint64_t v) {
    asm volatile("st.shared::cluster.u64 [%0], %1;" :: "r"(raddr), "l"(v) : "memory");
}
__device__ __forceinline__ void mbar_init(uint32_t a, uint32_t cnt) {
    asm volatile("mbarrier.init.shared.b64 [%0], %1;" :: "r"(a), "r"(cnt) : "memory");
}
__device__ __forceinline__ void mbar_arrive_peer_rel(uint32_t laddr, uint32_t peer) {
    asm volatile("{\n\t.reg .b32 r;\n\t"
                 "mapa.shared::cluster.u32 r, %0, %1;\n\t"
                 "mbarrier.arrive.release.cluster.shared::cluster.b64 _, [r];\n\t}"
                 :: "r"(laddr), "r"(peer) : "memory");
}
__device__ __forceinline__ void mbar_wait_acq(uint32_t a, uint32_t parity) {
    uint32_t done;
    asm volatile("{\n\t.reg .pred p;\n\t"
                 "mbarrier.try_wait.parity.acquire.cluster.shared::cta.b64 p, [%1], %2;\n\t"
                 "selp.b32 %0, 1, 0, p;\n\t}"
                 : "=r"(done) : "r"(a), "r"(parity) : "memory");
    if (!done) {
        asm volatile("{\n\t.reg .pred P1;\n\t"
                     "WL_%=:\n\t"
                     "mbarrier.try_wait.parity.acquire.cluster.shared::cta.b64 P1, [%0], %1;\n\t"
                     "@P1 bra.uni WD_%=;\n\t"
                     "bra.uni WL_%=;\n\t"
                     "WD_%=:\n\t}"
                     :: "r"(a), "r"(parity) : "memory");
    }
}
#define CLUSTER_ARRIVE() asm volatile("barrier.cluster.arrive.aligned;" ::: "memory")
#define CLUSTER_WAIT()   asm volatile("barrier.cluster.wait.aligned;" ::: "memory")

// packed (key, idx): u64 descending order == (key desc, idx asc)
__device__ __forceinline__ uint64_t pack_ki(int k, int i) {
    return ((uint64_t)(uint32_t)(k ^ 0x80000000) << 32) | (uint32_t)(~i);
}
__device__ __forceinline__ int unpack_k(uint64_t e) { return (int)((uint32_t)(e >> 32) ^ 0x80000000u); }
__device__ __forceinline__ int unpack_i(uint64_t e) { return (int)(~(uint32_t)e); }

// exact reference suppression: does winner (wb, wa) suppress box (cb, cab)?
__device__ __forceinline__ bool sup_test(float4 wb, float wa, float4 cb, float cab) {
    float iy1 = fmaxf(wb.x, cb.x);
    float ix1 = fmaxf(wb.y, cb.y);
    float iy2 = fminf(wb.z, cb.z);
    float ix2 = fminf(wb.w, cb.w);
    float inter = fmaxf(iy2 - iy1, 0.0f) * fmaxf(ix2 - ix1, 0.0f);
    float uni = wa + cab - inter;
    float d = fmaf(-IOU_C, uni, inter);
    return d > uni * HC;     // exact fl(inter/uni) > 0.45f
}

// ---------------- Phase 1: full-chip decode ----------------
__global__ __launch_bounds__(P1_NT)
void decode_kernel(const float* __restrict__ in)
{
    const int a = blockIdx.x * P1_NT + threadIdx.x;   // 0..9215
    const int b = blockIdx.y;
    const size_t o = (size_t)b * PADDED + a;

    if (a < ANCHORS) {
        const float* base = in + (size_t)b * (4 + NUM_CLASSES) * ANCHORS;
        float xc = base[0 * ANCHORS + a];
        float yc = base[1 * ANCHORS + a];
        float w  = base[2 * ANCHORS + a];
        float h  = base[3 * ANCHORS + a];

        float bs = base[4 * ANCHORS + a];
        int   bc = 0;
        #pragma unroll
        for (int c = 1; c < NUM_CLASSES; c++) {
            float v = base[(4 + c) * ANCHORS + a];
            if (v > bs) { bs = v; bc = c; }   // strict > = first max (jnp.argmax)
        }

        float hw = w * 0.5f;
        float hh = h * 0.5f;
        float y1 = fminf(fmaxf(yc - hh, 0.0f), 1.0f);
        float x1 = fminf(fmaxf(xc - hw, 0.0f), 1.0f);
        float y2 = fminf(fmaxf(yc + hh, 0.0f), 1.0f);
        float x2 = fminf(fmaxf(xc + hw, 0.0f), 1.0f);

        g_box[o] = make_float4(y1, x1, y2, x2);
        g_sc[o]  = (bs >= CONF) ? bs : -1.0f;
        g_cls[o] = (float)bc;
    } else {
        g_box[o] = make_float4(0.0f, 0.0f, 0.0f, 0.0f);
        g_sc[o]  = -1.0f;
        g_cls[o] = 0.0f;
    }
}

// one winner-slot IoU inside the scan (sentinel slot never suppresses)
#define SUP1(W, WA, J, CHECK)                                                  \
{   float q1 = fmaxf(W.x, ry1[k]);                                             \
    float q2 = fmaxf(W.y, rx1[k]);                                             \
    float q3 = fminf(W.z, ry2[k]);                                             \
    float q4 = fminf(W.w, rx2[k]);                                             \
    float it = fmaxf(q3 - q1, 0.0f) * fmaxf(q4 - q2, 0.0f);                    \
    float u  = WA + ab - it;                                                   \
    float e  = fmaf(-IOU_C, u, it);                                            \
    bool s = (e > u * HC);                                                     \
    if (CHECK) s = s || (gg == J);                                             \
    sup = sup || s;                                                            \
}

// suppression by 2 (or 3) winner slots + fresh per-thread top-2
#define SCAN_BODY(THREE, CHECK)                                                \
{                                                                              \
    int nk1 = NEG_INF_I, ni1 = 0, nk2 = NEG_INF_I, ni2 = 0;                    \
    _Pragma("unroll")                                                          \
    for (int k = 0; k < KPT; k++) {                                            \
        float v = rsc[k];                                                      \
        float ab = (ry2[k] - ry1[k]) * (rx2[k] - rx1[k]);                      \
        int gg = gbase + k;                                                    \
        bool sup = false;                                                      \
        SUP1(W0, WA0, J0, CHECK)                                               \
        SUP1(W1, WA1, J1, CHECK)                                               \
        if (THREE) { SUP1(W2, WA2, J2, CHECK) }                                \
        v = sup ? -1.0f : v;                                                   \
        rsc[k] = v;                                                            \
        int ik = __float_as_int(v);                                            \
        if (ik > nk1)      { nk2 = nk1; ni2 = ni1; nk1 = ik; ni1 = gg; }       \
        else if (ik > nk2) { nk2 = ik; ni2 = gg; }                             \
    }                                                                          \
    tk1 = nk1; ti1 = ni1; tk2 = nk2; ti2 = ni2;                                \
}

// ---------------- Phase 2: 2-CTA-cluster NMS, 64-entry cluster reduce ----------------
__global__ __launch_bounds__(NT, 1) __cluster_dims__(2, 1, 1)
void nms_kernel(float* __restrict__ out)
{
    extern __shared__ char smem[];
    float4* sbox = reinterpret_cast<float4*>(smem);                 // FULL boxes
    float*  scls = reinterpret_cast<float*>(smem + PADDED * 16);    // FULL classes

    __shared__ __align__(16) uint64_t s_own [2][2 * NWARPS];  // own warp top-2 (32)
    __shared__ __align__(16) uint64_t s_mail[2][2 * NWARPS];  // peer warp top-2 (32)
    __shared__ uint64_t s_mbar[2];

    const int tid  = threadIdx.x;
    const int lane = tid & 31;
    const int wid  = tid >> 5;
    const unsigned FULL = 0xffffffffu;
    uint32_t rank;
    asm("mov.u32 %0, %%cluster_ctarank;" : "=r"(rank));
    const uint32_t peer = rank ^ 1;
    const int b = blockIdx.x >> 1;

    const uint32_t mb0 = smem_u32(&s_mbar[0]);
    const uint32_t mb1 = smem_u32(&s_mbar[1]);
    // peer mailbox base addresses hoisted out of the loop
    const uint32_t pm0 = mapa_peer(smem_u32(&s_mail[0][0]), peer);
    const uint32_t pm1 = mapa_peer(smem_u32(&s_mail[1][0]), peer);

    if (tid == 0) { mbar_init(mb0, NWARPS); mbar_init(mb1, NWARPS); }

    // coalesced fill of the FULL arrays (both CTAs replicate)
    const float4* gb = g_box + (size_t)b * PADDED;
    const float*  gc = g_cls + (size_t)b * PADDED;
    for (int a = tid; a < PADDED; a += NT) { sbox[a] = gb[a]; scls[a] = gc[a]; }
    __syncthreads();

    CLUSTER_ARRIVE(); CLUSTER_WAIT();        // mbarrier init visible cluster-wide

    // register slice: this CTA owns global anchors [rank*HALF + t*9, +9)
    float ry1[KPT], rx1[KPT], ry2[KPT], rx2[KPT], rsc[KPT];
    const int gbase = (int)rank * HALF + tid * KPT;
    const float* gs = g_sc + (size_t)b * PADDED + gbase;
    int tk1 = NEG_INF_I, ti1 = 0, tk2 = NEG_INF_I, ti2 = 0;
    #pragma unroll
    for (int k = 0; k < KPT; k++) {
        float4 v = sbox[gbase + k];
        ry1[k] = v.x; rx1[k] = v.y; ry2[k] = v.z; rx2[k] = v.w;
        float sv = gs[k];
        rsc[k] = sv;
        int ik = __float_as_int(sv);
        if (ik > tk1)      { tk2 = tk1; ti2 = ti1; tk1 = ik; ti1 = gbase + k; }
        else if (ik > tk2) { tk2 = ik; ti2 = gbase + k; }
    }

    float* out_boxes = out + (size_t)b * MAX_DET * 4;
    float* out_cls   = out + (size_t)BATCH * MAX_DET * 4 + (size_t)b * MAX_DET;
    float* out_sc    = out + (size_t)BATCH * MAX_DET * 5 + (size_t)b * MAX_DET;
    float* out_nd    = out + (size_t)BATCH * MAX_DET * 6 + b;

    const uint64_t SENTMIN = pack_ki(NEG_INF_I, IDX_SENT);

    int ndet = 0, p = 0, ph0 = 0, ph1 = 0;
    while (ndet < MAX_DET) {
        // ---- Stage B: warp top-2 via redux.max + redux.min-on-index ----
        int m1 = __reduce_max_sync(FULL, tk1);
        int I1 = __reduce_min_sync(FULL, (tk1 == m1) ? ti1 : IDX_SENT);
        bool win = (ti1 == I1);               // anchor idx unique -> one lane
        int kx = win ? tk2 : tk1;
        int ix = win ? ti2 : ti1;
        int m2 = __reduce_max_sync(FULL, kx);
        int I2 = __reduce_min_sync(FULL, (kx == m2) ? ix : IDX_SENT);

        // ---- publish warp entries: own smem + peer smem (DSMEM), arrive ----
        // Parity double-buffer: rewriting buffers of parity p at pass t is safe
        // since our pass t-1 wait on mbar[p^1] required all peer arrives, each
        // program-ordered after that warp's pass t-2 reads of parity-p data.
        uint32_t mb = p ? mb1 : mb0;
        if (lane == 0) {
            uint64_t e1p = pack_ki(m1, I1);
            uint64_t e2p = pack_ki(m2, I2);
            s_own[p][2 * wid]     = e1p;
            s_own[p][2 * wid + 1] = e2p;
            uint32_t r = (p ? pm1 : pm0) + (uint32_t)(wid * 16);
            st_peer_u64(r,     e1p);
            st_peer_u64(r + 8, e2p);
            mbar_arrive_peer_rel(mb, peer);   // release: orders the two stores
        }
        __syncthreads();                       // own entries visible CTA-wide
        mbar_wait_acq(mb, (uint32_t)(p ? ph1 : ph0));   // all 16 peer arrives
        if (p) ph1 ^= 1; else ph0 ^= 1;

        // ---- Stage C: top-3 of the 64-entry multiset (2 per lane) ----
        uint64_t ea = s_own [p][lane];
        uint64_t eb = s_mail[p][lane];
        uint64_t hi = (ea > eb) ? ea : eb;
        uint64_t lo = (ea > eb) ? eb : ea;
        int mk0, mi0, mk1, mi1, mk2, mi2;
        #define CROUND(MK, MI)                                                 \
        {   int k = unpack_k(hi); int i = unpack_i(hi);                        \
            int M = __reduce_max_sync(FULL, k);                                \
            int I = __reduce_min_sync(FULL, (k == M) ? i : IDX_SENT);          \
            MK = M; MI = I;                                                    \
            if (k == M && i == I) { hi = lo; lo = SENTMIN; }                   \
        }
        CROUND(mk0, mi0) CROUND(mk1, mi1) CROUND(mk2, mi2)
        #undef CROUND

        if (mk0 < 0) break;                   // identical in both CTAs -> uniform

        // #3 is exact iff #1,#2 come from different warp-groups: then the true
        // global #3 is at worst #2 in its own group, hence present in the set.
        bool v1 = mk1 > 0;
        bool trust3 = v1 && ((mi0 / GROUPW) != (mi1 / GROUPW));
        bool v2 = (mk2 > 0) && trust3;

        float4 cb0 = sbox[mi0];
        float4 cb1 = sbox[v1 ? mi1 : 0];
        float4 cb2 = sbox[v2 ? mi2 : 0];
        float ca0 = (cb0.z - cb0.x) * (cb0.w - cb0.y);
        float ca1 = (cb1.z - cb1.x) * (cb1.w - cb1.y);
        float ca2 = (cb2.z - cb2.x) * (cb2.w - cb2.y);

        // ---- survivorship chain (uniform; exact reference tests) ----
        bool s10 = sup_test(cb0, ca0, cb1, ca1);
        bool s20 = sup_test(cb0, ca0, cb2, ca2);
        bool s21 = sup_test(cb1, ca1, cb2, ca2);

        int budget = MAX_DET - ndet;          // >= 1
        bool conf1 = v1 && (budget > 1) && !s10;
        int  cnt2  = 1 + (conf1 ? 1 : 0);
        bool conf2 = v2 && (cnt2 < budget) && !s20 && !(conf1 && s21);
        int  nw    = cnt2 + (conf2 ? 1 : 0);

        if (rank == 0 && tid == 0) {
            *reinterpret_cast<float4*>(out_boxes + ndet * 4) = cb0;   // 16B aligned
            out_cls[ndet] = scls[mi0];
            out_sc[ndet]  = __int_as_float(mk0);
            if (conf1) {
                int q = ndet + 1;
                *reinterpret_cast<float4*>(out_boxes + q * 4) = cb1;
                out_cls[q] = scls[mi1]; out_sc[q] = __int_as_float(mk1);
            }
            if (conf2) {
                int q = ndet + cnt2;
                *reinterpret_cast<float4*>(out_boxes + q * 4) = cb2;
                out_cls[q] = scls[mi2]; out_sc[q] = __int_as_float(mk2);
            }
        }

        // ---- winner slots: unconfirmed -> sentinel box (never suppresses) ----
        float4 W0 = cb0;                      float WA0 = ca0; int J0 = mi0;
        float4 W1 = conf1 ? cb1 : make_float4(-2.f, -2.f, -2.f, -2.f);
        float  WA1 = conf1 ? ca1 : 0.0f;      int J1 = conf1 ? mi1 : -1;
        float4 W2 = cb2;                      float WA2 = ca2; int J2 = mi2;  // read iff conf2

        ndet += nw;

        // Fast path: positive-area confirmed winners self-suppress via their own
        // IoU test (in == ab == aa exactly => e = 0.55*aa > aa*2^-26).
        bool bothpos = (ca0 > 0.0f) && (!conf1 || ca1 > 0.0f)
                    && (!conf2 || ca2 > 0.0f);                 // uniform
        if (ndet < MAX_DET && tk1 > 0) {      // dead slice -> state stays exact
            if (conf2) { if (bothpos) SCAN_BODY(1, 0) else SCAN_BODY(1, 1) }
            else       { if (bothpos) SCAN_BODY(0, 0) else SCAN_BODY(0, 1) }
        }

        p ^= 1;
    }

    // tail zero-fill (out is poisoned; reference emits zeros for !ok slots)
    if (rank == 0) {
        for (int i = ndet + tid; i < MAX_DET; i += NT) {
            out_boxes[i * 4 + 0] = 0.0f;
            out_boxes[i * 4 + 1] = 0.0f;
            out_boxes[i * 4 + 2] = 0.0f;
            out_boxes[i * 4 + 3] = 0.0f;
            out_cls[i] = 0.0f;
            out_sc[i]  = 0.0f;
        }
        if (tid == 0) *out_nd = (float)ndet;
    }

    CLUSTER_ARRIVE(); CLUSTER_WAIT();    // no CTA exits while peer may signal it
}

extern "C" void kernel_launch(void* const* d_in, const int* in_sizes, int n_in,
                              void* d_out, int out_size)
{
    (void)in_sizes; (void)n_in; (void)out_size;
    const float* in = (const float*)d_in[0];
    float* out = (float*)d_out;

    cudaFuncSetAttribute(nms_kernel,
                         cudaFuncAttributeMaxDynamicSharedMemorySize, SMEM_BYTES);

    dim3 g1(P1_GRIDX, BATCH);
    decode_kernel<<<g1, P1_NT>>>(in);
    nms_kernel<<<2 * BATCH, NT, SMEM_BYTES>>>(out);
}